// round 4
// baseline (speedup 1.0000x reference)
#include <cuda_runtime.h>
#include <math.h>

#define RW   512
#define NT   180
#define PAD  112
#define PW   736              // padded width
#define RSPLIT 4
#define RCHUNK 128            // RW / RSPLIT

// texel table: [layout 0=normal,1=transposed][PW*PW]
// q[y][x] = (im0[y][x], im1[y][x], im0[y][x+1], im1[y][x+1])  (layout coords)
__device__ float4 g_q[2][PW * PW];
// partial sums: [rsplit][n*RW*NT + c*NT + t]
__device__ float g_part[RSPLIT][2 * RW * NT];

__global__ void __launch_bounds__(256)
prep_kernel(const float* __restrict__ img)
{
    const int idx = blockIdx.x * blockDim.x + threadIdx.x;   // 0 .. PW*PW-1
    const int l   = blockIdx.y;                              // layout
    const int px  = idx % PW;
    const int py  = idx / PW;

    int r0, c0, r1, c1;
    if (l == 0) { r0 = py - PAD; c0 = px - PAD; r1 = r0;     c1 = c0 + 1; }
    else        { r0 = px - PAD; c0 = py - PAD; r1 = r0 + 1; c1 = c0;     }

    float4 v = make_float4(0.f, 0.f, 0.f, 0.f);
    if ((unsigned)r0 < (unsigned)RW && (unsigned)c0 < (unsigned)RW) {
        v.x = img[(size_t)r0 * RW + c0];
        v.y = img[(size_t)(RW * RW) + (size_t)r0 * RW + c0];
    }
    if ((unsigned)r1 < (unsigned)RW && (unsigned)c1 < (unsigned)RW) {
        v.z = img[(size_t)r1 * RW + c1];
        v.w = img[(size_t)(RW * RW) + (size_t)r1 * RW + c1];
    }
    g_q[l][py * PW + px] = v;
}

__global__ void __launch_bounds__(128)
radon_kernel()
{
    const int c     = blockIdx.x * blockDim.x + threadIdx.x; // 0..511
    const int t     = blockIdx.y;                            // 0..179
    const int rbase = blockIdx.z * RCHUNK;                   // r chunk start

    float s, ct;
    sincosf((float)t * 0.017453292519943295f, &s, &ct);

    // Pick layout whose contiguous ("fast") coordinate moves most with c.
    const bool T = fabsf(s) > fabsf(ct);
    const float dfc = T ? -s : ct;    // d(fast)/dc
    const float dfr = T ?  ct : s;    // d(fast)/dr
    const float dsc = T ?  ct : -s;   // d(slow)/dc
    const float dsr = T ?  s  : ct;   // d(slow)/dr

    // Shear lane start in r to minimize lane-to-lane slow-coordinate step.
    int k0 = 0;
    {
        float b0 = fabsf(dsc);
        float b1 = fabsf(dsc + dsr);
        float b2 = fabsf(dsc - dsr);
        if (b1 < b0) { b0 = b1; k0 = 1; }
        if (b2 < b0) {          k0 = -1; }
    }

    const float4* __restrict__ buf = &g_q[T ? 1 : 0][0];

    const float u  = (float)c - 255.5f;
    const float bf = fmaf(dfc, u, 255.5f + (float)PAD);   // fast = bf + dfr*v
    const float bs = fmaf(dsc, u, 255.5f + (float)PAD);   // slow = bs + dsr*v

    const int roff = (k0 * (c & 31) + RCHUNK) & (RCHUNK - 1);

    float acc0 = 0.0f, acc1 = 0.0f;

    #pragma unroll 4
    for (int j = 0; j < RCHUNK; ++j) {
        const int   r  = rbase + ((j + roff) & (RCHUNK - 1));
        const float v  = (float)r - 255.5f;
        const float fa = fmaf(dfr, v, bf);
        const float sl = fmaf(dsr, v, bs);

        const float ff = floorf(fa);
        const float fs = floorf(sl);
        const float wf = fa - ff;
        const float ws = sl - fs;
        const int   fi = (int)ff;
        const int   si = (int)fs;

        const float4* __restrict__ p = buf + si * PW + fi;
        const float4 A = __ldg(p);          // v00_0, v00_1, v01_0, v01_1
        const float4 B = __ldg(p + PW);     // v10_0, v10_1, v11_0, v11_1

        const float top0 = fmaf(wf, A.z - A.x, A.x);
        const float top1 = fmaf(wf, A.w - A.y, A.y);
        const float bot0 = fmaf(wf, B.z - B.x, B.x);
        const float bot1 = fmaf(wf, B.w - B.y, B.y);
        acc0 += fmaf(ws, bot0 - top0, top0);
        acc1 += fmaf(ws, bot1 - top1, top1);
    }

    g_part[blockIdx.z][(size_t)c * NT + t]            = acc0;
    g_part[blockIdx.z][(size_t)(RW + c) * NT + t]     = acc1;
}

__global__ void __launch_bounds__(256)
reduce_kernel(float* __restrict__ out)
{
    const int i = blockIdx.x * blockDim.x + threadIdx.x;   // 0 .. 2*RW*NT-1
    float v = g_part[0][i] + g_part[1][i] + g_part[2][i] + g_part[3][i];
    out[i] = v * (1.0f / 512.0f);
}

extern "C" void kernel_launch(void* const* d_in, const int* in_sizes, int n_in,
                              void* d_out, int out_size)
{
    const float* x = (const float*)d_in[0];
    float* out = (float*)d_out;

    dim3 pblock(256, 1, 1);
    dim3 pgrid((PW * PW) / 256, 2, 1);      // PW*PW = 541696 = 2116*256
    prep_kernel<<<pgrid, pblock>>>(x);

    dim3 block(128, 1, 1);
    dim3 grid(RW / 128, NT, RSPLIT);        // 4 x 180 x 4 = 2880 CTAs
    radon_kernel<<<grid, block>>>();

    reduce_kernel<<<(2 * RW * NT) / 256, 256>>>(out);
}

// round 6
// speedup vs baseline: 1.1361x; 1.1361x over previous
#include <cuda_runtime.h>
#include <math.h>

#define RW   512
#define NT   180
#define PAD  112
#define PW   736              // padded width

// texel table: [layout 0=normal,1=transposed][PW*PW]
// q[y][x] = (im0[y][x], im1[y][x], im0[y][x+1], im1[y][x+1])  (layout coords)
__device__ float4 g_q[2][PW * PW];

__global__ void __launch_bounds__(256)
prep_kernel(const float* __restrict__ img)
{
    const int idx = blockIdx.x * blockDim.x + threadIdx.x;   // 0 .. PW*PW-1
    const int l   = blockIdx.y;                              // layout
    const int px  = idx % PW;
    const int py  = idx / PW;

    int r0, c0, r1, c1;
    if (l == 0) { r0 = py - PAD; c0 = px - PAD; r1 = r0;     c1 = c0 + 1; }
    else        { r0 = px - PAD; c0 = py - PAD; r1 = r0 + 1; c1 = c0;     }

    float4 v = make_float4(0.f, 0.f, 0.f, 0.f);
    if ((unsigned)r0 < (unsigned)RW && (unsigned)c0 < (unsigned)RW) {
        v.x = img[(size_t)r0 * RW + c0];
        v.y = img[(size_t)(RW * RW) + (size_t)r0 * RW + c0];
    }
    if ((unsigned)r1 < (unsigned)RW && (unsigned)c1 < (unsigned)RW) {
        v.z = img[(size_t)r1 * RW + c1];
        v.w = img[(size_t)(RW * RW) + (size_t)r1 * RW + c1];
    }
    g_q[l][py * PW + px] = v;
}

__global__ void __launch_bounds__(128)
radon_kernel(float* __restrict__ out)
{
    const int c = blockIdx.x * blockDim.x + threadIdx.x;   // 0..511
    const int t = blockIdx.y;                              // 0..179

    float s, ct;
    sincosf((float)t * 0.017453292519943295f, &s, &ct);

    // Pick layout whose contiguous ("fast") coordinate moves most with c.
    const bool T = fabsf(s) > fabsf(ct);
    const float dfc = T ? -s : ct;    // d(fast)/dc
    const float dfr = T ?  ct : s;    // d(fast)/dr
    const float dsc = T ?  ct : -s;   // d(slow)/dc  (|dsc| <= |dsr|)
    const float dsr = T ?  s  : ct;   // d(slow)/dr  (|dsr| >= 0.707)

    // Per-lane rounded shear: lane L starts its r-sweep at offset
    // k(L) = round(-(dsc/dsr) * L).  Then lane L's slow coordinate is
    // slow_0 + dsr*(alpha*L - round(alpha*L)), i.e. within +-0.5 of lane 0
    // for EVERY lane -> each warp request touches <= 2 consecutive rows.
    // r order is a free permutation of 0..511, so the sum is unchanged.
    const int   L     = c & 31;
    const float alpha = dsc / dsr;
    const int   kL    = __float2int_rn(-alpha * (float)L);
    const int   roff  = (kL + RW) & (RW - 1);

    const float4* __restrict__ buf = &g_q[T ? 1 : 0][0];

    const float u  = (float)c - 255.5f;
    const float bf = fmaf(dfc, u, 255.5f + (float)PAD);   // fast = bf + dfr*v
    const float bs = fmaf(dsc, u, 255.5f + (float)PAD);   // slow = bs + dsr*v

    float acc0 = 0.0f, acc1 = 0.0f;

    #pragma unroll 4
    for (int j = 0; j < RW; ++j) {
        const int   r  = (j + roff) & (RW - 1);
        const float v  = (float)r - 255.5f;
        const float fa = fmaf(dfr, v, bf);
        const float sl = fmaf(dsr, v, bs);

        const float ff = floorf(fa);
        const float fs = floorf(sl);
        const float wf = fa - ff;
        const float ws = sl - fs;
        const int   fi = (int)ff;
        const int   si = (int)fs;

        const float4* __restrict__ p = buf + si * PW + fi;
        const float4 A = __ldg(p);          // v00_0, v00_1, v01_0, v01_1
        const float4 B = __ldg(p + PW);     // v10_0, v10_1, v11_0, v11_1

        const float top0 = fmaf(wf, A.z - A.x, A.x);
        const float top1 = fmaf(wf, A.w - A.y, A.y);
        const float bot0 = fmaf(wf, B.z - B.x, B.x);
        const float bot1 = fmaf(wf, B.w - B.y, B.y);
        acc0 += fmaf(ws, bot0 - top0, top0);
        acc1 += fmaf(ws, bot1 - top1, top1);
    }

    // out shape (N, 1, W, NT): out[n][0][c][t]
    out[(size_t)c * NT + t]        = acc0 * (1.0f / 512.0f);
    out[(size_t)(RW + c) * NT + t] = acc1 * (1.0f / 512.0f);
}

extern "C" void kernel_launch(void* const* d_in, const int* in_sizes, int n_in,
                              void* d_out, int out_size)
{
    const float* x = (const float*)d_in[0];
    float* out = (float*)d_out;

    dim3 pblock(256, 1, 1);
    dim3 pgrid((PW * PW) / 256, 2, 1);      // PW*PW = 541696 = 2116*256
    prep_kernel<<<pgrid, pblock>>>(x);

    dim3 block(128, 1, 1);
    dim3 grid(RW / 128, NT, 1);
    radon_kernel<<<grid, block>>>(out);
}

// round 7
// speedup vs baseline: 1.2860x; 1.1320x over previous
#include <cuda_runtime.h>
#include <cuda_fp16.h>
#include <math.h>

#define RW   512
#define NT   180
#define PAD  112
#define PW   736              // padded width

// texel table: [layout 0=normal,1=transposed][PW*PW]
// texel.x = half2(im0[x],   im1[x])     (layout coords, row y)
// texel.y = half2(im0[x+1], im1[x+1])
__device__ uint2 g_q[2][PW * PW];

__global__ void __launch_bounds__(256)
prep_kernel(const float* __restrict__ img)
{
    const int idx = blockIdx.x * blockDim.x + threadIdx.x;   // 0 .. PW*PW-1
    const int l   = blockIdx.y;                              // layout
    const int px  = idx % PW;
    const int py  = idx / PW;

    int r0, c0, r1, c1;
    if (l == 0) { r0 = py - PAD; c0 = px - PAD; r1 = r0;     c1 = c0 + 1; }
    else        { r0 = px - PAD; c0 = py - PAD; r1 = r0 + 1; c1 = c0;     }

    float a0 = 0.f, a1 = 0.f, b0 = 0.f, b1 = 0.f;
    if ((unsigned)r0 < (unsigned)RW && (unsigned)c0 < (unsigned)RW) {
        a0 = img[(size_t)r0 * RW + c0];
        a1 = img[(size_t)(RW * RW) + (size_t)r0 * RW + c0];
    }
    if ((unsigned)r1 < (unsigned)RW && (unsigned)c1 < (unsigned)RW) {
        b0 = img[(size_t)r1 * RW + c1];
        b1 = img[(size_t)(RW * RW) + (size_t)r1 * RW + c1];
    }

    __half2 h0 = __floats2half2_rn(a0, a1);
    __half2 h1 = __floats2half2_rn(b0, b1);
    uint2 t;
    t.x = reinterpret_cast<unsigned&>(h0);
    t.y = reinterpret_cast<unsigned&>(h1);
    g_q[l][py * PW + px] = t;
}

__global__ void __launch_bounds__(128)
radon_kernel(float* __restrict__ out)
{
    const int c = blockIdx.x * blockDim.x + threadIdx.x;   // 0..511
    const int t = blockIdx.y;                              // 0..179

    float s, ct;
    sincosf((float)t * 0.017453292519943295f, &s, &ct);

    // Pick layout whose contiguous ("fast") coordinate moves most with c.
    const bool T = fabsf(s) > fabsf(ct);
    const float dfc = T ? -s : ct;    // d(fast)/dc
    const float dfr = T ?  ct : s;    // d(fast)/dr
    const float dsc = T ?  ct : -s;   // d(slow)/dc  (|dsc| <= |dsr|)
    const float dsr = T ?  s  : ct;   // d(slow)/dr  (|dsr| >= 0.707)

    // Per-lane rounded shear: lane L starts its r-sweep at offset
    // k(L) = round(-(dsc/dsr) * L), keeping every lane's slow coordinate
    // within +-0.5 of lane 0 on every iteration -> each warp request
    // touches <= 2 consecutive rows.  r order is a free permutation.
    const int   L     = c & 31;
    const float alpha = dsc / dsr;
    const int   kL    = __float2int_rn(-alpha * (float)L);
    const int   roff  = (kL + RW) & (RW - 1);

    const uint2* __restrict__ buf = &g_q[T ? 1 : 0][0];

    const float u  = (float)c - 255.5f;
    const float bf = fmaf(dfc, u, 255.5f + (float)PAD);   // fast = bf + dfr*v
    const float bs = fmaf(dsc, u, 255.5f + (float)PAD);   // slow = bs + dsr*v

    float acc0 = 0.0f, acc1 = 0.0f;

    #pragma unroll 4
    for (int j = 0; j < RW; ++j) {
        const int   r  = (j + roff) & (RW - 1);
        const float v  = (float)r - 255.5f;
        const float fa = fmaf(dfr, v, bf);
        const float sl = fmaf(dsr, v, bs);

        const float ff = floorf(fa);
        const float fs = floorf(sl);
        const float wf = fa - ff;
        const float ws = sl - fs;
        const int   fi = (int)ff;
        const int   si = (int)fs;

        const uint2* __restrict__ p = buf + si * PW + fi;
        const uint2 A = __ldg(p);          // row si:   (v00_0,v00_1),(v01_0,v01_1)
        const uint2 B = __ldg(p + PW);     // row si+1: (v10_0,v10_1),(v11_0,v11_1)

        const float2 f00 = __half22float2(reinterpret_cast<const __half2&>(A.x));
        const float2 f01 = __half22float2(reinterpret_cast<const __half2&>(A.y));
        const float2 f10 = __half22float2(reinterpret_cast<const __half2&>(B.x));
        const float2 f11 = __half22float2(reinterpret_cast<const __half2&>(B.y));

        const float top0 = fmaf(wf, f01.x - f00.x, f00.x);
        const float top1 = fmaf(wf, f01.y - f00.y, f00.y);
        const float bot0 = fmaf(wf, f11.x - f10.x, f10.x);
        const float bot1 = fmaf(wf, f11.y - f10.y, f10.y);
        acc0 += fmaf(ws, bot0 - top0, top0);
        acc1 += fmaf(ws, bot1 - top1, top1);
    }

    // out shape (N, 1, W, NT): out[n][0][c][t]
    out[(size_t)c * NT + t]        = acc0 * (1.0f / 512.0f);
    out[(size_t)(RW + c) * NT + t] = acc1 * (1.0f / 512.0f);
}

extern "C" void kernel_launch(void* const* d_in, const int* in_sizes, int n_in,
                              void* d_out, int out_size)
{
    const float* x = (const float*)d_in[0];
    float* out = (float*)d_out;

    dim3 pblock(256, 1, 1);
    dim3 pgrid((PW * PW) / 256, 2, 1);      // PW*PW = 541696 = 2116*256
    prep_kernel<<<pgrid, pblock>>>(x);

    dim3 block(128, 1, 1);
    dim3 grid(RW / 128, NT, 1);
    radon_kernel<<<grid, block>>>(out);
}

// round 8
// speedup vs baseline: 1.5393x; 1.1969x over previous
#include <cuda_runtime.h>
#include <cuda_fp16.h>
#include <math.h>

#define RW   512
#define NT   180
#define PAD  112
#define PW   736              // padded width
#define RSPLIT 2
#define RCHUNK 256            // RW / RSPLIT

// texel table: [layout 0=normal,1=transposed][PW*PW]
// texel.x = half2(im0[x],   im1[x])     (layout coords, row y)
// texel.y = half2(im0[x+1], im1[x+1])
__device__ uint2 g_q[2][PW * PW];
__device__ float g_part[RSPLIT][2 * RW * NT];

__global__ void __launch_bounds__(256)
prep_kernel(const float* __restrict__ img)
{
    const int idx = blockIdx.x * blockDim.x + threadIdx.x;   // 0 .. PW*PW-1
    const int l   = blockIdx.y;                              // layout
    const int px  = idx % PW;
    const int py  = idx / PW;

    int r0, c0, r1, c1;
    if (l == 0) { r0 = py - PAD; c0 = px - PAD; r1 = r0;     c1 = c0 + 1; }
    else        { r0 = px - PAD; c0 = py - PAD; r1 = r0 + 1; c1 = c0;     }

    float a0 = 0.f, a1 = 0.f, b0 = 0.f, b1 = 0.f;
    if ((unsigned)r0 < (unsigned)RW && (unsigned)c0 < (unsigned)RW) {
        a0 = img[(size_t)r0 * RW + c0];
        a1 = img[(size_t)(RW * RW) + (size_t)r0 * RW + c0];
    }
    if ((unsigned)r1 < (unsigned)RW && (unsigned)c1 < (unsigned)RW) {
        b0 = img[(size_t)r1 * RW + c1];
        b1 = img[(size_t)(RW * RW) + (size_t)r1 * RW + c1];
    }

    __half2 h0 = __floats2half2_rn(a0, a1);
    __half2 h1 = __floats2half2_rn(b0, b1);
    uint2 t;
    t.x = reinterpret_cast<unsigned&>(h0);
    t.y = reinterpret_cast<unsigned&>(h1);
    g_q[l][py * PW + px] = t;
}

__global__ void __launch_bounds__(128)
radon_kernel()
{
    const int c     = blockIdx.x * blockDim.x + threadIdx.x; // 0..511
    const int t     = blockIdx.y;                            // 0..179
    const int rbase = blockIdx.z * RCHUNK;

    float s, ct;
    sincosf((float)t * 0.017453292519943295f, &s, &ct);

    // Pick layout whose contiguous ("fast") coordinate moves most with c.
    const bool T = fabsf(s) > fabsf(ct);
    const float dfc = T ? -s : ct;    // d(fast)/dc
    const float dfr = T ?  ct : s;    // d(fast)/dr
    const float dsc = T ?  ct : -s;   // d(slow)/dc  (|dsc| <= |dsr|)
    const float dsr = T ?  s  : ct;   // d(slow)/dr  (|dsr| >= 0.707)

    // Per-lane rounded shear: lane L rotates its r-sweep start by
    // k(L) = round(-(dsc/dsr)*L), keeping every lane's slow coordinate
    // within +-0.5 of lane 0 (mod chunk wrap) -> <= 2 rows per request.
    const int   L     = c & 31;
    const float alpha = dsc / dsr;
    const int   kL    = __float2int_rn(-alpha * (float)L);
    const int   roff  = (kL + RCHUNK) & (RCHUNK - 1);

    const uint2* __restrict__ buf = &g_q[T ? 1 : 0][0];

    const float u  = (float)c - 255.5f;
    const float bf = fmaf(dfc, u, 255.5f + (float)PAD);   // fast = bf + dfr*v
    const float bs = fmaf(dsc, u, 255.5f + (float)PAD);   // slow = bs + dsr*v

    float acc0 = 0.0f, acc1 = 0.0f;

    #pragma unroll 4
    for (int j = 0; j < RCHUNK; ++j) {
        const int   r  = rbase + ((j + roff) & (RCHUNK - 1));
        const float v  = (float)r - 255.5f;
        const float fa = fmaf(dfr, v, bf);
        const float sl = fmaf(dsr, v, bs);

        const float ff = floorf(fa);
        const float fs = floorf(sl);
        const int   fi = (int)ff;
        const int   si = (int)fs;

        const __half2 wf2 = __float2half2_rn(fa - ff);
        const __half2 ws2 = __float2half2_rn(sl - fs);

        const uint2* __restrict__ p = buf + si * PW + fi;
        const uint2 A = __ldg(p);          // row si:   (v00),(v01) pairs
        const uint2 B = __ldg(p + PW);     // row si+1: (v10),(v11) pairs

        const __half2 a0 = reinterpret_cast<const __half2&>(A.x);
        const __half2 a1 = reinterpret_cast<const __half2&>(A.y);
        const __half2 b0 = reinterpret_cast<const __half2&>(B.x);
        const __half2 b1 = reinterpret_cast<const __half2&>(B.y);

        const __half2 top = __hfma2(wf2, __hsub2(a1, a0), a0);
        const __half2 bot = __hfma2(wf2, __hsub2(b1, b0), b0);
        const __half2 res = __hfma2(ws2, __hsub2(bot, top), top);

        const float2 rf = __half22float2(res);
        acc0 += rf.x;
        acc1 += rf.y;
    }

    g_part[blockIdx.z][(size_t)c * NT + t]        = acc0;
    g_part[blockIdx.z][(size_t)(RW + c) * NT + t] = acc1;
}

__global__ void __launch_bounds__(256)
reduce_kernel(float* __restrict__ out)
{
    const int i = blockIdx.x * blockDim.x + threadIdx.x;   // 0 .. 2*RW*NT-1
    out[i] = (g_part[0][i] + g_part[1][i]) * (1.0f / 512.0f);
}

extern "C" void kernel_launch(void* const* d_in, const int* in_sizes, int n_in,
                              void* d_out, int out_size)
{
    const float* x = (const float*)d_in[0];
    float* out = (float*)d_out;

    dim3 pblock(256, 1, 1);
    dim3 pgrid((PW * PW) / 256, 2, 1);      // PW*PW = 541696 = 2116*256
    prep_kernel<<<pgrid, pblock>>>(x);

    dim3 block(128, 1, 1);
    dim3 grid(RW / 128, NT, RSPLIT);        // 4 x 180 x 2 = 1440 CTAs
    radon_kernel<<<grid, block>>>();

    reduce_kernel<<<(2 * RW * NT) / 256, 256>>>(out);
}

// round 9
// speedup vs baseline: 1.6388x; 1.0646x over previous
#include <cuda_runtime.h>
#include <cuda_fp16.h>
#include <math.h>

#define RW   512
#define NT   180
#define PAD  112
#define PW   736              // padded width
#define RSPLIT 2
#define RCHUNK 256            // RW / RSPLIT

// packed half2(im0,im1) images: [layout 0=normal,1=transposed][RW*RW]
__device__ unsigned g_pimg[2][RW * RW];
// combined 2x2 texel table: [layout][PW*PW]
// g_q[l][y*PW+x] = { h2(y,x), h2(y,x+1), h2(y+1,x), h2(y+1,x+1) }
__device__ uint4 g_q[2][PW * PW];
__device__ float g_part[RSPLIT][2 * RW * NT];

__global__ void __launch_bounds__(256)
pack_kernel(const float* __restrict__ img)
{
    const int idx = blockIdx.x * blockDim.x + threadIdx.x;   // 0 .. RW*RW-1
    const int l   = blockIdx.y;
    const int x   = idx % RW;
    const int y   = idx / RW;
    // layout 0: buffer(y,x) = image(row y, col x)
    // layout 1: buffer(y,x) = image(row x, col y)
    const int rr = l ? x : y;
    const int cc = l ? y : x;
    const float a = img[(size_t)rr * RW + cc];
    const float b = img[(size_t)(RW * RW) + (size_t)rr * RW + cc];
    __half2 h = __floats2half2_rn(a, b);
    g_pimg[l][y * RW + x] = reinterpret_cast<unsigned&>(h);
}

__global__ void __launch_bounds__(256)
texel_kernel()
{
    const int idx = blockIdx.x * blockDim.x + threadIdx.x;   // 0 .. PW*PW-1
    const int l   = blockIdx.y;
    const int px  = idx % PW;
    const int py  = idx / PW;
    const int x   = px - PAD;
    const int y   = py - PAD;

    const unsigned* __restrict__ pim = &g_pimg[l][0];
    const bool xv0 = (unsigned)x       < (unsigned)RW;
    const bool xv1 = (unsigned)(x + 1) < (unsigned)RW;
    const bool yv0 = (unsigned)y       < (unsigned)RW;
    const bool yv1 = (unsigned)(y + 1) < (unsigned)RW;

    uint4 t = make_uint4(0u, 0u, 0u, 0u);
    if (yv0) {
        const unsigned* row = pim + y * RW;
        if (xv0) t.x = row[x];
        if (xv1) t.y = row[x + 1];
    }
    if (yv1) {
        const unsigned* row = pim + (y + 1) * RW;
        if (xv0) t.z = row[x];
        if (xv1) t.w = row[x + 1];
    }
    g_q[l][py * PW + px] = t;
}

__global__ void __launch_bounds__(128)
radon_kernel()
{
    const int c     = blockIdx.x * blockDim.x + threadIdx.x; // 0..511
    const int t     = blockIdx.y;                            // 0..179
    const int rbase = blockIdx.z * RCHUNK;

    float s, ct;
    sincosf((float)t * 0.017453292519943295f, &s, &ct);

    // Pick layout whose contiguous ("fast") coordinate moves most with c.
    const bool T = fabsf(s) > fabsf(ct);
    const float dfc = T ? -s : ct;    // d(fast)/dc
    const float dfr = T ?  ct : s;    // d(fast)/dr
    const float dsc = T ?  ct : -s;   // d(slow)/dc  (|dsc| <= |dsr|)
    const float dsr = T ?  s  : ct;   // d(slow)/dr  (|dsr| >= 0.707)

    // Per-lane rounded shear keeps every lane's slow coordinate within
    // +-0.5 of lane 0 -> each warp request touches <= 2 consecutive rows
    // (both captured inside the combined texel).  r order is free.
    const int   L     = c & 31;
    const float alpha = dsc / dsr;
    const int   kL    = __float2int_rn(-alpha * (float)L);
    const int   roff  = (kL + RCHUNK) & (RCHUNK - 1);

    const uint4* __restrict__ buf = &g_q[T ? 1 : 0][0];

    const float u  = (float)c - 255.5f;
    const float bf = fmaf(dfc, u, 255.5f + (float)PAD);   // fast = bf + dfr*v
    const float bs = fmaf(dsc, u, 255.5f + (float)PAD);   // slow = bs + dsr*v

    float acc0 = 0.0f, acc1 = 0.0f;

    #pragma unroll 4
    for (int j = 0; j < RCHUNK; j += 2) {
        __half2 resp[2];
        #pragma unroll
        for (int k = 0; k < 2; ++k) {
            const int   r  = rbase + ((j + k + roff) & (RCHUNK - 1));
            const float v  = (float)r - 255.5f;
            const float fa = fmaf(dfr, v, bf);
            const float sl = fmaf(dsr, v, bs);

            const float ff = floorf(fa);
            const float fs = floorf(sl);
            const int   fi = (int)ff;
            const int   si = (int)fs;

            const __half2 wf2 = __float2half2_rn(fa - ff);
            const __half2 ws2 = __float2half2_rn(sl - fs);

            const uint4 A = __ldg(buf + si * PW + fi);
            const __half2 a00 = reinterpret_cast<const __half2&>(A.x);
            const __half2 a01 = reinterpret_cast<const __half2&>(A.y);
            const __half2 a10 = reinterpret_cast<const __half2&>(A.z);
            const __half2 a11 = reinterpret_cast<const __half2&>(A.w);

            const __half2 top = __hfma2(wf2, __hsub2(a01, a00), a00);
            const __half2 bot = __hfma2(wf2, __hsub2(a11, a10), a10);
            resp[k] = __hfma2(ws2, __hsub2(bot, top), top);
        }
        const float2 rf = __half22float2(__hadd2(resp[0], resp[1]));
        acc0 += rf.x;
        acc1 += rf.y;
    }

    g_part[blockIdx.z][(size_t)c * NT + t]        = acc0;
    g_part[blockIdx.z][(size_t)(RW + c) * NT + t] = acc1;
}

__global__ void __launch_bounds__(256)
reduce_kernel(float* __restrict__ out)
{
    const int i = blockIdx.x * blockDim.x + threadIdx.x;   // 0 .. 2*RW*NT-1
    out[i] = (g_part[0][i] + g_part[1][i]) * (1.0f / 512.0f);
}

extern "C" void kernel_launch(void* const* d_in, const int* in_sizes, int n_in,
                              void* d_out, int out_size)
{
    const float* x = (const float*)d_in[0];
    float* out = (float*)d_out;

    pack_kernel<<<dim3((RW * RW) / 256, 2, 1), 256>>>(x);
    texel_kernel<<<dim3((PW * PW) / 256, 2, 1), 256>>>();   // PW*PW = 2116*256

    dim3 block(128, 1, 1);
    dim3 grid(RW / 128, NT, RSPLIT);        // 4 x 180 x 2 = 1440 CTAs
    radon_kernel<<<grid, block>>>();

    reduce_kernel<<<(2 * RW * NT) / 256, 256>>>(out);
}

// round 11
// speedup vs baseline: 1.7948x; 1.0952x over previous
#include <cuda_runtime.h>
#include <cuda_fp16.h>
#include <math.h>

#define RW   512
#define NT   180
#define PAD  112
#define PW   736              // padded width
#define RSPLIT 4
#define RCHUNK 128            // RW / RSPLIT
#define IB   514              // interior band: texels with a corner in-image

// packed half2(im0,im1) images: [layout 0=normal,1=transposed][RW*RW]
__device__ unsigned g_pimg[2][RW * RW];
// combined 2x2 texel table: [layout][PW*PW]; pure-padding texels stay 0 (BSS)
// g_q[l][y*PW+x] = { h2(y,x), h2(y,x+1), h2(y+1,x), h2(y+1,x+1) }
__device__ uint4 g_q[2][PW * PW];
__device__ float g_part[RSPLIT][2 * RW * NT];

__global__ void __launch_bounds__(256)
pack_kernel(const float* __restrict__ img)
{
    const int idx = blockIdx.x * blockDim.x + threadIdx.x;   // 0 .. RW*RW-1
    const int l   = blockIdx.y;
    const int x   = idx % RW;
    const int y   = idx / RW;
    const int rr = l ? x : y;
    const int cc = l ? y : x;
    const float a = img[(size_t)rr * RW + cc];
    const float b = img[(size_t)(RW * RW) + (size_t)rr * RW + cc];
    __half2 h = __floats2half2_rn(a, b);
    g_pimg[l][y * RW + x] = reinterpret_cast<unsigned&>(h);
}

__global__ void __launch_bounds__(256)
texel_kernel()
{
    const int idx = blockIdx.x * blockDim.x + threadIdx.x;   // 0 .. IB*IB-1
    if (idx >= IB * IB) return;
    const int l  = blockIdx.y;
    const int px = idx % IB + (PAD - 1);
    const int py = idx / IB + (PAD - 1);
    const int x  = px - PAD;
    const int y  = py - PAD;

    const unsigned* __restrict__ pim = &g_pimg[l][0];
    const bool xv0 = (unsigned)x       < (unsigned)RW;
    const bool xv1 = (unsigned)(x + 1) < (unsigned)RW;

    uint4 t = make_uint4(0u, 0u, 0u, 0u);
    if ((unsigned)y < (unsigned)RW) {
        const unsigned* row = pim + y * RW;
        if (xv0) t.x = row[x];
        if (xv1) t.y = row[x + 1];
    }
    if ((unsigned)(y + 1) < (unsigned)RW) {
        const unsigned* row = pim + (y + 1) * RW;
        if (xv0) t.z = row[x];
        if (xv1) t.w = row[x + 1];
    }
    g_q[l][py * PW + px] = t;
}

__global__ void __launch_bounds__(128)
radon_kernel()
{
    const int c     = blockIdx.x * blockDim.x + threadIdx.x; // 0..511
    const int t     = blockIdx.y;                            // 0..179
    const int rbase = blockIdx.z * RCHUNK;

    float s, ct;
    sincosf((float)t * 0.017453292519943295f, &s, &ct);

    // Pick layout whose contiguous ("fast") coordinate moves most with c.
    const bool T = fabsf(s) > fabsf(ct);
    const float dfc = T ? -s : ct;    // d(fast)/dc
    const float dfr = T ?  ct : s;    // d(fast)/dr
    const float dsc = T ?  ct : -s;   // d(slow)/dc  (|dsc| <= |dsr|)
    const float dsr = T ?  s  : ct;   // d(slow)/dr  (|dsr| >= 0.707)

    // Rounded shear with OUTER mod-512: lane L sweeps r = (rbase+kL+j)&511.
    // Lanes stay r-contiguous everywhere except the single global wrap
    // (~6% of iterations total), so each warp request touches <= 2-3
    // consecutive rows (captured by the combined 2x2 texel).
    // Union over the RSPLIT blocks covers each r in 0..511 exactly once.
    const int   L     = c & 31;
    const float alpha = dsc / dsr;
    const int   kL    = __float2int_rn(-alpha * (float)L);

    const uint4* __restrict__ buf = &g_q[T ? 1 : 0][0];

    const float u  = (float)c - 255.5f;
    const float bf = fmaf(dfc, u, 255.5f + (float)PAD);   // fast = bf + dfr*v
    const float bs = fmaf(dsc, u, 255.5f + (float)PAD);   // slow = bs + dsr*v

    float acc0 = 0.0f, acc1 = 0.0f;

    #pragma unroll 4
    for (int j = 0; j < RCHUNK; j += 2) {
        __half2 resp[2];
        #pragma unroll
        for (int k = 0; k < 2; ++k) {
            const int   r  = (rbase + kL + j + k) & (RW - 1);
            const float v  = (float)r - 255.5f;
            const float fa = fmaf(dfr, v, bf);
            const float sl = fmaf(dsr, v, bs);

            const float ff = floorf(fa);
            const float fs = floorf(sl);
            const int   fi = (int)ff;
            const int   si = (int)fs;

            const __half2 wf2 = __float2half2_rn(fa - ff);
            const __half2 ws2 = __float2half2_rn(sl - fs);

            const uint4 A = __ldg(buf + si * PW + fi);
            const __half2 a00 = reinterpret_cast<const __half2&>(A.x);
            const __half2 a01 = reinterpret_cast<const __half2&>(A.y);
            const __half2 a10 = reinterpret_cast<const __half2&>(A.z);
            const __half2 a11 = reinterpret_cast<const __half2&>(A.w);

            const __half2 top = __hfma2(wf2, __hsub2(a01, a00), a00);
            const __half2 bot = __hfma2(wf2, __hsub2(a11, a10), a10);
            resp[k] = __hfma2(ws2, __hsub2(bot, top), top);
        }
        const float2 rf = __half22float2(__hadd2(resp[0], resp[1]));
        acc0 += rf.x;
        acc1 += rf.y;
    }

    g_part[blockIdx.z][(size_t)c * NT + t]        = acc0;
    g_part[blockIdx.z][(size_t)(RW + c) * NT + t] = acc1;
}

__global__ void __launch_bounds__(256)
reduce_kernel(float* __restrict__ out)
{
    const int i = blockIdx.x * blockDim.x + threadIdx.x;   // float4 index
    const float4 p0 = reinterpret_cast<const float4*>(g_part[0])[i];
    const float4 p1 = reinterpret_cast<const float4*>(g_part[1])[i];
    const float4 p2 = reinterpret_cast<const float4*>(g_part[2])[i];
    const float4 p3 = reinterpret_cast<const float4*>(g_part[3])[i];
    float4 o;
    o.x = (p0.x + p1.x + p2.x + p3.x) * (1.0f / 512.0f);
    o.y = (p0.y + p1.y + p2.y + p3.y) * (1.0f / 512.0f);
    o.z = (p0.z + p1.z + p2.z + p3.z) * (1.0f / 512.0f);
    o.w = (p0.w + p1.w + p2.w + p3.w) * (1.0f / 512.0f);
    reinterpret_cast<float4*>(out)[i] = o;
}

extern "C" void kernel_launch(void* const* d_in, const int* in_sizes, int n_in,
                              void* d_out, int out_size)
{
    const float* x = (const float*)d_in[0];
    float* out = (float*)d_out;

    pack_kernel<<<dim3((RW * RW) / 256, 2, 1), 256>>>(x);
    texel_kernel<<<dim3((IB * IB + 255) / 256, 2, 1), 256>>>();

    dim3 block(128, 1, 1);
    dim3 grid(RW / 128, NT, RSPLIT);        // 4 x 180 x 4 = 2880 CTAs
    radon_kernel<<<grid, block>>>();

    reduce_kernel<<<(2 * RW * NT / 4) / 256, 256>>>(out);
}